// round 3
// baseline (speedup 1.0000x reference)
#include <cuda_runtime.h>
#include <cstdint>
#include <cstddef>

// Problem constants
#define T_   1024
#define B_   8
#define E_   512
#define H_   8
#define D_   64
#define BH_  (B_ * H_)          // 64
#define M_   (T_ * B_)          // 8192
#define K3E  (3 * E_)           // 1536
#define SCALE_ 0.125f

#define TT_  (T_ * T_)
#define OUT_OFF2 (2 * (size_t)T_ * B_ * E_)
#define BTT_ ((size_t)B_ * T_ * T_)

// -------------------- scratch (device globals) ------------------------------
__device__ float g_qkv_r[(size_t)M_ * K3E];
__device__ float g_qkv_i[(size_t)M_ * K3E];
__device__ float g_aw_r[(size_t)BH_ * TT_];   // logits, then p in place
__device__ float g_aw_i[(size_t)BH_ * TT_];
__device__ float g_attn_r[(size_t)M_ * E_];
__device__ float g_attn_i[(size_t)M_ * E_];

// -------------------- helpers ------------------------------------------------
__device__ __forceinline__ uint32_t f2tf(float x) {
    uint32_t r;
    asm("cvt.rna.tf32.f32 %0, %1;" : "=r"(r) : "f"(x));
    return r;
}

__device__ __forceinline__ void mma8(float* c, const uint32_t* a, const uint32_t* b) {
    asm volatile(
        "mma.sync.aligned.m16n8k8.row.col.f32.tf32.tf32.f32 "
        "{%0,%1,%2,%3},{%4,%5,%6,%7},{%8,%9},{%0,%1,%2,%3};"
        : "+f"(c[0]), "+f"(c[1]), "+f"(c[2]), "+f"(c[3])
        : "r"(a[0]), "r"(a[1]), "r"(a[2]), "r"(a[3]), "r"(b[0]), "r"(b[1]));
}

__device__ __forceinline__ void cp16(uint32_t s, const float* g) {
    asm volatile("cp.async.cg.shared.global [%0], [%1], 16;"
                 :: "r"(s), "l"((unsigned long long)__cvta_generic_to_global(g)));
}

// ---------------------------------------------------------------------------
// Complex GEMM on tensor cores (tf32): C = (Ar+iAi)@(Br+iBi)^T + bias
// A: [M,K] row-major, B: [N,K] row-major. Used for the two linear layers.
// ---------------------------------------------------------------------------
__global__ __launch_bounds__(256, 2)
void cmma_linear(const float* __restrict__ Ar, const float* __restrict__ Ai,
                 long lda,
                 const float* __restrict__ Br, const float* __restrict__ Bi,
                 long ldb,
                 float* __restrict__ Cr, float* __restrict__ Ci,
                 long ldc,
                 const float* __restrict__ biasr, const float* __restrict__ biasi,
                 int K)
{
    extern __shared__ float sm[];
    constexpr int AS = 128 * 36;
    constexpr int BS = 64 * 36;
    float* AsR = sm;
    float* AsI = sm + 2 * AS;
    float* BsR = sm + 4 * AS;
    float* BsI = sm + 4 * AS + 2 * BS;

    const int tid  = threadIdx.x;
    const int lane = tid & 31;
    const int warp = tid >> 5;
    const int wm   = warp & 3;
    const int wn   = warp >> 2;
    const int grp  = lane >> 2;
    const int quad = lane & 3;

    const int m0 = blockIdx.y << 7;
    const int n0 = blockIdx.x << 6;

    const uint32_t sAsR = (uint32_t)__cvta_generic_to_shared(AsR);
    const uint32_t sAsI = (uint32_t)__cvta_generic_to_shared(AsI);
    const uint32_t sBsR = (uint32_t)__cvta_generic_to_shared(BsR);
    const uint32_t sBsI = (uint32_t)__cvta_generic_to_shared(BsI);

    float cr[2][4][4], ci[2][4][4];
#pragma unroll
    for (int mi = 0; mi < 2; mi++)
#pragma unroll
        for (int ni = 0; ni < 4; ni++)
#pragma unroll
            for (int r = 0; r < 4; r++) { cr[mi][ni][r] = 0.f; ci[mi][ni][r] = 0.f; }

    const int NC = K >> 5;

    auto load_chunk = [&](int c, int buf) {
        const int k0 = c << 5;
#pragma unroll
        for (int j = 0; j < 4; j++) {
            int idx = tid + j * 256;
            int row = idx >> 3;
            int c4  = (idx & 7) << 2;
            uint32_t so = (uint32_t)((buf * AS + row * 36 + c4) * 4);
            cp16(sAsR + so, Ar + (size_t)(m0 + row) * lda + k0 + c4);
            cp16(sAsI + so, Ai + (size_t)(m0 + row) * lda + k0 + c4);
        }
#pragma unroll
        for (int j = 0; j < 2; j++) {
            int idx = tid + j * 256;
            int row = idx >> 3;
            int c4  = (idx & 7) << 2;
            uint32_t so = (uint32_t)((buf * BS + row * 36 + c4) * 4);
            cp16(sBsR + so, Br + (size_t)(n0 + row) * ldb + k0 + c4);
            cp16(sBsI + so, Bi + (size_t)(n0 + row) * ldb + k0 + c4);
        }
    };

    load_chunk(0, 0);
    asm volatile("cp.async.commit_group;");

    for (int c = 0; c < NC; c++) {
        if (c + 1 < NC) load_chunk(c + 1, (c + 1) & 1);
        asm volatile("cp.async.commit_group;");
        asm volatile("cp.async.wait_group 1;");
        __syncthreads();

        const float* aR = AsR + (c & 1) * AS;
        const float* aI = AsI + (c & 1) * AS;
        const float* bR = BsR + (c & 1) * BS;
        const float* bI = BsI + (c & 1) * BS;

#pragma unroll
        for (int ks = 0; ks < 4; ks++) {
            const int kk = ks * 8 + quad;
            uint32_t afr[2][4], afi[2][4];
#pragma unroll
            for (int mi = 0; mi < 2; mi++) {
                int r0 = wm * 32 + mi * 16 + grp;
                afr[mi][0] = f2tf(aR[r0 * 36 + kk]);
                afr[mi][1] = f2tf(aR[(r0 + 8) * 36 + kk]);
                afr[mi][2] = f2tf(aR[r0 * 36 + kk + 4]);
                afr[mi][3] = f2tf(aR[(r0 + 8) * 36 + kk + 4]);
                afi[mi][0] = f2tf(aI[r0 * 36 + kk]);
                afi[mi][1] = f2tf(aI[(r0 + 8) * 36 + kk]);
                afi[mi][2] = f2tf(aI[r0 * 36 + kk + 4]);
                afi[mi][3] = f2tf(aI[(r0 + 8) * 36 + kk + 4]);
            }
#pragma unroll
            for (int ni = 0; ni < 4; ni++) {
                int nn = wn * 32 + ni * 8 + grp;
                uint32_t bfr[2], bfi[2], bfx[2];
                bfr[0] = f2tf(bR[nn * 36 + kk]);
                bfr[1] = f2tf(bR[nn * 36 + kk + 4]);
                bfi[0] = f2tf(bI[nn * 36 + kk]);
                bfi[1] = f2tf(bI[nn * 36 + kk + 4]);
                bfx[0] = bfi[0] ^ 0x80000000u;
                bfx[1] = bfi[1] ^ 0x80000000u;
#pragma unroll
                for (int mi = 0; mi < 2; mi++) {
                    mma8(cr[mi][ni], afr[mi], bfr);
                    mma8(cr[mi][ni], afi[mi], bfx);   // -ai*bi
                    mma8(ci[mi][ni], afi[mi], bfr);
                    mma8(ci[mi][ni], afr[mi], bfi);   // +ar*bi
                }
            }
        }
        __syncthreads();
    }

#pragma unroll
    for (int mi = 0; mi < 2; mi++) {
#pragma unroll
        for (int ni = 0; ni < 4; ni++) {
            int m = m0 + wm * 32 + mi * 16 + grp;
            int n = n0 + wn * 32 + ni * 8 + quad * 2;
            float br0 = biasr[n], br1 = biasr[n + 1];
            float bi0 = biasi[n], bi1 = biasi[n + 1];
            float2 v;
            v.x = cr[mi][ni][0] + br0; v.y = cr[mi][ni][1] + br1;
            *(float2*)(Cr + (size_t)m * ldc + n) = v;
            v.x = cr[mi][ni][2] + br0; v.y = cr[mi][ni][3] + br1;
            *(float2*)(Cr + (size_t)(m + 8) * ldc + n) = v;
            v.x = ci[mi][ni][0] + bi0; v.y = ci[mi][ni][1] + bi1;
            *(float2*)(Ci + (size_t)m * ldc + n) = v;
            v.x = ci[mi][ni][2] + bi0; v.y = ci[mi][ni][3] + bi1;
            *(float2*)(Ci + (size_t)(m + 8) * ldc + n) = v;
        }
    }
}

// ---------------------------------------------------------------------------
// Fused attention: scores -> softmax stats -> p -> PV, per (bh, 128 t-rows).
// Phase 1: logits on tensor cores (Q strip smem-resident, K tiles streamed),
//          running row (max,sum) flash-style; raw logits -> g_aw.
// Phase 2: re-read logits (L2), p=exp(x-m)*inv -> g_aw (for avg) + smem,
//          PV complex MMA accumulate; write attn in [T,B,E] layout.
// Smem map (floats): Ap0[128*68] | Ap1 | BK[buf][comp][64*68] | rm[256] |
//                    rs[256] | stg[2][2][128][2]  -> 36352 floats = 145408 B
// ---------------------------------------------------------------------------
__global__ __launch_bounds__(256, 1)
void fused_attn()
{
    extern __shared__ float sm[];
    float* Ap0 = sm;                 // Q (phase1) / p_r (phase2) [128][68]
    float* Ap1 = sm + 8704;          // [128][68]
    float* BK0 = sm + 17408;         // BK(buf,comp) = BK0 + (buf*2+comp)*4352
    float* rmv = sm + 34816;         // [2][128] running max
    float* rsv = sm + 35072;         // [2][128] running sum -> inv
    float* stg = sm + 35328;         // [2 comp][2 wn][128][2]

    const int tid  = threadIdx.x;
    const int lane = tid & 31;
    const int warp = tid >> 5;
    const int wm   = warp & 3;
    const int wn   = warp >> 2;
    const int grp  = lane >> 2;
    const int quad = lane & 3;

    const int bh = blockIdx.y;
    const int b  = bh >> 3, h = bh & 7;
    const int t0 = blockIdx.x << 7;

    const uint32_t sbase = (uint32_t)__cvta_generic_to_shared(sm);
    const size_t awbase = (size_t)bh * TT_;

    rmv[tid] = -1e30f;
    rsv[tid] = 0.f;

    // ---- load Q strip (128 x 64, both components) ----
#pragma unroll
    for (int j = 0; j < 8; j++) {
        int lin = tid + j * 256;
        int row = lin >> 4, c4 = (lin & 15) << 2;
        size_t g = ((size_t)(t0 + row) * B_ + b) * K3E + h * D_ + c4;
        uint32_t so = sbase + (uint32_t)((row * 68 + c4) * 4);
        cp16(so, g_qkv_r + g);
        cp16(so + 8704 * 4, g_qkv_i + g);
    }

    auto load_kv = [&](int s0, int buf, int off) {
#pragma unroll
        for (int j = 0; j < 4; j++) {
            int lin = tid + j * 256;
            int row = lin >> 4, c4 = (lin & 15) << 2;
            size_t g = ((size_t)(s0 + row) * B_ + b) * K3E + off + h * D_ + c4;
            uint32_t so = sbase + (uint32_t)((17408 + buf * 2 * 4352 + row * 68 + c4) * 4);
            cp16(so, g_qkv_r + g);
            cp16(so + 4352 * 4, g_qkv_i + g);
        }
    };

    load_kv(0, 0, E_);
    asm volatile("cp.async.commit_group;");

    float cr[2][4][4], ci[2][4][4];

    // ================= Phase 1: logits + running softmax stats ==============
    for (int s = 0; s < 16; s++) {
        if (s < 15) load_kv((s + 1) << 6, (s + 1) & 1, E_);
        asm volatile("cp.async.commit_group;");
        asm volatile("cp.async.wait_group 1;");
        __syncthreads();

        const float* bR = BK0 + (s & 1) * 2 * 4352;
        const float* bI = bR + 4352;

#pragma unroll
        for (int mi = 0; mi < 2; mi++)
#pragma unroll
            for (int ni = 0; ni < 4; ni++)
#pragma unroll
                for (int r = 0; r < 4; r++) { cr[mi][ni][r] = 0.f; ci[mi][ni][r] = 0.f; }

#pragma unroll
        for (int ks = 0; ks < 8; ks++) {
            const int kk = ks * 8 + quad;
            uint32_t afr[2][4], afi[2][4];
#pragma unroll
            for (int mi = 0; mi < 2; mi++) {
                int r0 = wm * 32 + mi * 16 + grp;
                afr[mi][0] = f2tf(Ap0[r0 * 68 + kk]);
                afr[mi][1] = f2tf(Ap0[(r0 + 8) * 68 + kk]);
                afr[mi][2] = f2tf(Ap0[r0 * 68 + kk + 4]);
                afr[mi][3] = f2tf(Ap0[(r0 + 8) * 68 + kk + 4]);
                afi[mi][0] = f2tf(Ap1[r0 * 68 + kk]);
                afi[mi][1] = f2tf(Ap1[(r0 + 8) * 68 + kk]);
                afi[mi][2] = f2tf(Ap1[r0 * 68 + kk + 4]);
                afi[mi][3] = f2tf(Ap1[(r0 + 8) * 68 + kk + 4]);
            }
#pragma unroll
            for (int ni = 0; ni < 4; ni++) {
                int nn = wn * 32 + ni * 8 + grp;
                uint32_t bfr[2], bfi[2], bfx[2];
                bfr[0] = f2tf(bR[nn * 68 + kk]);
                bfr[1] = f2tf(bR[nn * 68 + kk + 4]);
                bfi[0] = f2tf(bI[nn * 68 + kk]);
                bfi[1] = f2tf(bI[nn * 68 + kk + 4]);
                bfx[0] = bfi[0] ^ 0x80000000u;
                bfx[1] = bfi[1] ^ 0x80000000u;
#pragma unroll
                for (int mi = 0; mi < 2; mi++) {
                    // conj(K): s_r = qr.kr + qi.ki ; s_i = qi.kr - qr.ki
                    mma8(cr[mi][ni], afr[mi], bfr);
                    mma8(cr[mi][ni], afi[mi], bfi);
                    mma8(ci[mi][ni], afi[mi], bfr);
                    mma8(ci[mi][ni], afr[mi], bfx);
                }
            }
        }

#pragma unroll
        for (int mi = 0; mi < 2; mi++)
#pragma unroll
            for (int ni = 0; ni < 4; ni++)
#pragma unroll
                for (int r = 0; r < 4; r++) { cr[mi][ni][r] *= SCALE_; ci[mi][ni][r] *= SCALE_; }

        // --- per-row partial (max, sumexp) across this warp's 32 cols ---
#pragma unroll
        for (int c = 0; c < 2; c++) {
            float (*acc)[4][4] = c ? ci : cr;
#pragma unroll
            for (int mi = 0; mi < 2; mi++)
#pragma unroll
                for (int h2 = 0; h2 < 2; h2++) {
                    float mx = -1e30f;
#pragma unroll
                    for (int ni = 0; ni < 4; ni++) {
                        mx = fmaxf(mx, acc[mi][ni][h2 * 2]);
                        mx = fmaxf(mx, acc[mi][ni][h2 * 2 + 1]);
                    }
                    mx = fmaxf(mx, __shfl_xor_sync(0xffffffffu, mx, 1));
                    mx = fmaxf(mx, __shfl_xor_sync(0xffffffffu, mx, 2));
                    float se = 0.f;
#pragma unroll
                    for (int ni = 0; ni < 4; ni++) {
                        se += __expf(acc[mi][ni][h2 * 2] - mx);
                        se += __expf(acc[mi][ni][h2 * 2 + 1] - mx);
                    }
                    se += __shfl_xor_sync(0xffffffffu, se, 1);
                    se += __shfl_xor_sync(0xffffffffu, se, 2);
                    if (quad == 0) {
                        int row = wm * 32 + mi * 16 + h2 * 8 + grp;
                        float* p = stg + (((c * 2 + wn) * 128) + row) * 2;
                        p[0] = mx; p[1] = se;
                    }
                }
        }
        __syncthreads();
        {
            int c = tid >> 7, row = tid & 127;
            const float* p0 = stg + ((c * 2 + 0) * 128 + row) * 2;
            const float* p1 = stg + ((c * 2 + 1) * 128 + row) * 2;
            float m0 = p0[0], s0v = p0[1], m1 = p1[0], s1v = p1[1];
            float tm = fmaxf(m0, m1);
            float ts = s0v * __expf(m0 - tm) + s1v * __expf(m1 - tm);
            float om = rmv[tid];
            float nm = fmaxf(om, tm);
            rsv[tid] = rsv[tid] * __expf(om - nm) + ts * __expf(tm - nm);
            rmv[tid] = nm;
        }

        // --- write raw logits tile to g_aw ---
#pragma unroll
        for (int mi = 0; mi < 2; mi++)
#pragma unroll
            for (int ni = 0; ni < 4; ni++) {
                int m = t0 + wm * 32 + mi * 16 + grp;
                int n = (s << 6) + wn * 32 + ni * 8 + quad * 2;
                size_t o = awbase + (size_t)m * T_ + n;
                float2 v;
                v.x = cr[mi][ni][0]; v.y = cr[mi][ni][1];
                *(float2*)(g_aw_r + o) = v;
                v.x = cr[mi][ni][2]; v.y = cr[mi][ni][3];
                *(float2*)(g_aw_r + o + 8 * T_) = v;
                v.x = ci[mi][ni][0]; v.y = ci[mi][ni][1];
                *(float2*)(g_aw_i + o) = v;
                v.x = ci[mi][ni][2]; v.y = ci[mi][ni][3];
                *(float2*)(g_aw_i + o + 8 * T_) = v;
            }
        __syncthreads();
    }

    asm volatile("cp.async.wait_group 0;");
    rsv[tid] = 1.f / rsv[tid];
    __syncthreads();

    // ================= Phase 2: p + PV accumulate ===========================
#pragma unroll
    for (int mi = 0; mi < 2; mi++)
#pragma unroll
        for (int ni = 0; ni < 4; ni++)
#pragma unroll
            for (int r = 0; r < 4; r++) { cr[mi][ni][r] = 0.f; ci[mi][ni][r] = 0.f; }

    load_kv(0, 0, 2 * E_);
    asm volatile("cp.async.commit_group;");

    for (int s = 0; s < 16; s++) {
        if (s < 15) load_kv((s + 1) << 6, (s + 1) & 1, 2 * E_);
        asm volatile("cp.async.commit_group;");

        // logits -> p (gmem read, mostly L2) ; write p back + stage into smem
#pragma unroll
        for (int c = 0; c < 2; c++) {
            float* gbuf = c ? g_aw_i : g_aw_r;
            float* abuf = c ? Ap1 : Ap0;
            const float* rmc = rmv + c * 128;
            const float* rsc = rsv + c * 128;
#pragma unroll
            for (int j = 0; j < 8; j++) {
                int lin = tid + j * 256;
                int row = lin >> 4, c4 = (lin & 15) << 2;
                size_t o = awbase + (size_t)(t0 + row) * T_ + (s << 6) + c4;
                float4 v = *(const float4*)(gbuf + o);
                float m = rmc[row], iv = rsc[row];
                v.x = __expf(v.x - m) * iv;
                v.y = __expf(v.y - m) * iv;
                v.z = __expf(v.z - m) * iv;
                v.w = __expf(v.w - m) * iv;
                *(float4*)(gbuf + o) = v;
                *(float4*)(abuf + row * 68 + c4) = v;
            }
        }
        asm volatile("cp.async.wait_group 1;");
        __syncthreads();

        const float* bR = BK0 + (s & 1) * 2 * 4352;   // V tile [s][d]
        const float* bI = bR + 4352;

#pragma unroll
        for (int ks = 0; ks < 8; ks++) {
            const int kk = ks * 8 + quad;
            uint32_t afr[2][4], afi[2][4];
#pragma unroll
            for (int mi = 0; mi < 2; mi++) {
                int r0 = wm * 32 + mi * 16 + grp;
                afr[mi][0] = f2tf(Ap0[r0 * 68 + kk]);
                afr[mi][1] = f2tf(Ap0[(r0 + 8) * 68 + kk]);
                afr[mi][2] = f2tf(Ap0[r0 * 68 + kk + 4]);
                afr[mi][3] = f2tf(Ap0[(r0 + 8) * 68 + kk + 4]);
                afi[mi][0] = f2tf(Ap1[r0 * 68 + kk]);
                afi[mi][1] = f2tf(Ap1[(r0 + 8) * 68 + kk]);
                afi[mi][2] = f2tf(Ap1[r0 * 68 + kk + 4]);
                afi[mi][3] = f2tf(Ap1[(r0 + 8) * 68 + kk + 4]);
            }
#pragma unroll
            for (int ni = 0; ni < 4; ni++) {
                int nn = wn * 32 + ni * 8 + grp;
                uint32_t bfr[2], bfi[2], bfx[2];
                bfr[0] = f2tf(bR[kk * 68 + nn]);
                bfr[1] = f2tf(bR[(kk + 4) * 68 + nn]);
                bfi[0] = f2tf(bI[kk * 68 + nn]);
                bfi[1] = f2tf(bI[(kk + 4) * 68 + nn]);
                bfx[0] = bfi[0] ^ 0x80000000u;
                bfx[1] = bfi[1] ^ 0x80000000u;
#pragma unroll
                for (int mi = 0; mi < 2; mi++) {
                    // conj(V): o_r = pr.vr + pi.vi ; o_i = pi.vr - pr.vi
                    mma8(cr[mi][ni], afr[mi], bfr);
                    mma8(cr[mi][ni], afi[mi], bfi);
                    mma8(ci[mi][ni], afi[mi], bfr);
                    mma8(ci[mi][ni], afr[mi], bfx);
                }
            }
        }
        __syncthreads();
    }

    // ---- epilogue: attn in [T, B, E] layout ----
#pragma unroll
    for (int mi = 0; mi < 2; mi++)
#pragma unroll
        for (int ni = 0; ni < 4; ni++) {
            int m = t0 + wm * 32 + mi * 16 + grp;
            int n = wn * 32 + ni * 8 + quad * 2;
            size_t o = ((size_t)m * B_ + b) * E_ + h * D_ + n;
            size_t o8 = o + (size_t)8 * B_ * E_;
            float2 v;
            v.x = cr[mi][ni][0]; v.y = cr[mi][ni][1];
            *(float2*)(g_attn_r + o) = v;
            v.x = cr[mi][ni][2]; v.y = cr[mi][ni][3];
            *(float2*)(g_attn_r + o8) = v;
            v.x = ci[mi][ni][0]; v.y = ci[mi][ni][1];
            *(float2*)(g_attn_i + o) = v;
            v.x = ci[mi][ni][2]; v.y = ci[mi][ni][3];
            *(float2*)(g_attn_i + o8) = v;
        }
}

// ---------------------------------------------------------------------------
// Head-average of attention weights -> d_out tail [2, B, T, T]
// ---------------------------------------------------------------------------
__global__ __launch_bounds__(256) void avg_kernel(float* __restrict__ out)
{
    const int t = blockIdx.x;
    const int b = blockIdx.y;
    const int s = threadIdx.x << 2;

    float4 sr = {0.f, 0.f, 0.f, 0.f};
    float4 si = {0.f, 0.f, 0.f, 0.f};
#pragma unroll
    for (int h = 0; h < H_; h++) {
        size_t base = ((size_t)(b * H_ + h) * T_ + t) * T_ + s;
        float4 r  = *(const float4*)&g_aw_r[base];
        float4 im = *(const float4*)&g_aw_i[base];
        sr.x += r.x;  sr.y += r.y;  sr.z += r.z;  sr.w += r.w;
        si.x += im.x; si.y += im.y; si.z += im.z; si.w += im.w;
    }
    const float inv = 1.0f / (float)H_;
    sr.x *= inv; sr.y *= inv; sr.z *= inv; sr.w *= inv;
    si.x *= inv; si.y *= inv; si.z *= inv; si.w *= inv;

    size_t o = ((size_t)b * T_ + t) * T_ + s;
    *(float4*)&out[OUT_OFF2 + o]        = sr;
    *(float4*)&out[OUT_OFF2 + BTT_ + o] = si;
}

// ---------------------------------------------------------------------------
extern "C" void kernel_launch(void* const* d_in, const int* in_sizes, int n_in,
                              void* d_out, int out_size)
{
    const float* query_r = (const float*)d_in[0];
    const float* query_i = (const float*)d_in[1];
    const float* W_qkv_r = (const float*)d_in[2];
    const float* W_qkv_i = (const float*)d_in[3];
    const float* b_qkv_r = (const float*)d_in[4];
    const float* b_qkv_i = (const float*)d_in[5];
    const float* W_out_r = (const float*)d_in[6];
    const float* W_out_i = (const float*)d_in[7];
    const float* b_out_r = (const float*)d_in[8];
    const float* b_out_i = (const float*)d_in[9];
    float* out = (float*)d_out;

    float *gqkvr, *gqkvi, *gatr, *gati;
    cudaGetSymbolAddress((void**)&gqkvr, g_qkv_r);
    cudaGetSymbolAddress((void**)&gqkvi, g_qkv_i);
    cudaGetSymbolAddress((void**)&gatr, g_attn_r);
    cudaGetSymbolAddress((void**)&gati, g_attn_i);

    const int SMEM_LIN   = (4 * 128 * 36 + 4 * 64 * 36) * 4;   // 110592 B
    const int SMEM_FUSED = 36352 * 4;                          // 145408 B

    cudaFuncSetAttribute((const void*)cmma_linear,
                         cudaFuncAttributeMaxDynamicSharedMemorySize, SMEM_LIN);
    cudaFuncSetAttribute((const void*)fused_attn,
                         cudaFuncAttributeMaxDynamicSharedMemorySize, SMEM_FUSED);

    dim3 blk(256);

    // 1) QKV complex linear: [8192,512] @ [1536,512]^T -> g_qkv
    cmma_linear<<<dim3(K3E / 64, M_ / 128), blk, SMEM_LIN>>>(
        query_r, query_i, E_,
        W_qkv_r, W_qkv_i, E_,
        gqkvr, gqkvi, K3E,
        b_qkv_r, b_qkv_i, E_);

    // 2) Fused scores + softmax + PV (aw -> g_aw, attn -> g_attn)
    fused_attn<<<dim3(T_ / 128, BH_), blk, SMEM_FUSED>>>();

    // 3) Head-averaged attention weights -> d_out tail
    avg_kernel<<<dim3(T_, B_), blk>>>(out);

    // 4) Output complex linear -> d_out head (out_r, out_i)
    cmma_linear<<<dim3(E_ / 64, M_ / 128), blk, SMEM_LIN>>>(
        gatr, gati, E_,
        W_out_r, W_out_i, E_,
        out, out + (size_t)M_ * E_, E_,
        b_out_r, b_out_i, E_);
}

// round 4
// speedup vs baseline: 1.5266x; 1.5266x over previous
#include <cuda_runtime.h>
#include <cstdint>
#include <cstddef>

// Problem constants
#define T_   1024
#define B_   8
#define E_   512
#define H_   8
#define D_   64
#define BH_  (B_ * H_)          // 64
#define M_   (T_ * B_)          // 8192
#define K3E  (3 * E_)           // 1536
#define SCALE_ 0.125f

#define TT_  (T_ * T_)
#define OUT_OFF2 (2 * (size_t)T_ * B_ * E_)
#define BTT_ ((size_t)B_ * T_ * T_)

// -------------------- scratch (device globals) ------------------------------
__device__ float g_qkv_r[(size_t)M_ * K3E];
__device__ float g_qkv_i[(size_t)M_ * K3E];
__device__ float g_aw_r[(size_t)BH_ * TT_];
__device__ float g_aw_i[(size_t)BH_ * TT_];
__device__ float g_attn_r[(size_t)M_ * E_];
__device__ float g_attn_i[(size_t)M_ * E_];
// pre-rounded (tf32) copies of inputs
__device__ float g_qt_r[(size_t)M_ * E_];
__device__ float g_qt_i[(size_t)M_ * E_];
__device__ float g_wqkv_r[(size_t)K3E * E_];
__device__ float g_wqkv_i[(size_t)K3E * E_];
__device__ float g_wout_r[(size_t)E_ * E_];
__device__ float g_wout_i[(size_t)E_ * E_];

// -------------------- helpers ------------------------------------------------
__device__ __forceinline__ uint32_t f2tf(float x) {
    uint32_t r;
    asm("cvt.rna.tf32.f32 %0, %1;" : "=r"(r) : "f"(x));
    return r;
}
__device__ __forceinline__ float tfround(float x) {
    return __uint_as_float(f2tf(x));
}

__device__ __forceinline__ void mma8(float* c, const uint32_t* a, const uint32_t* b) {
    asm volatile(
        "mma.sync.aligned.m16n8k8.row.col.f32.tf32.tf32.f32 "
        "{%0,%1,%2,%3},{%4,%5,%6,%7},{%8,%9},{%0,%1,%2,%3};"
        : "+f"(c[0]), "+f"(c[1]), "+f"(c[2]), "+f"(c[3])
        : "r"(a[0]), "r"(a[1]), "r"(a[2]), "r"(a[3]), "r"(b[0]), "r"(b[1]));
}

__device__ __forceinline__ void cp16(uint32_t s, const float* g) {
    asm volatile("cp.async.cg.shared.global [%0], [%1], 16;"
                 :: "r"(s), "l"((unsigned long long)__cvta_generic_to_global(g)));
}

// ---------------------------------------------------------------------------
// Pre-round fp32 -> tf32-valued fp32, vectorized
// ---------------------------------------------------------------------------
__global__ __launch_bounds__(256) void round_kernel(
    const float* __restrict__ src, float* __restrict__ dst, int n4)
{
    int i = blockIdx.x * 256 + threadIdx.x;
    if (i < n4) {
        float4 v = ((const float4*)src)[i];
        v.x = tfround(v.x); v.y = tfround(v.y);
        v.z = tfround(v.z); v.w = tfround(v.w);
        ((float4*)dst)[i] = v;
    }
}

// ---------------------------------------------------------------------------
// Complex GEMM on tensor cores (tf32).
//   C = (Ar + iAi) @ op(Br + iBi) [+ bias] [* alpha]
//   A: [M,K] row-major; B: [N,K] (B_KN=false) or [K,N] (B_KN=true) row-major.
//   CONJ=false: cr = ar*br - ai*bi ; ci = ai*br + ar*bi
//   CONJ=true : cr = ar*br + ai*bi ; ci = ai*br - ar*bi   (B conjugated)
//   CVT_A/CVT_B: apply tf32 rounding at fragment load (false if pre-rounded).
//   ROUND_C: store outputs tf32-rounded (for operands of later GEMMs).
//   Batched via blockIdx.z: zb=z>>3, zh=z&7.
// ---------------------------------------------------------------------------
template <bool CONJ, bool B_KN, bool CVT_A, bool CVT_B, bool ROUND_C>
__global__ __launch_bounds__(256, 2)
void cmma_kernel(const float* __restrict__ Ar, const float* __restrict__ Ai,
                 long lda, long sA1, long sA2,
                 const float* __restrict__ Br, const float* __restrict__ Bi,
                 long ldb, long sB1, long sB2,
                 float* __restrict__ Cr, float* __restrict__ Ci,
                 long ldc, long sC1, long sC2,
                 const float* __restrict__ biasr, const float* __restrict__ biasi,
                 float alpha, int K)
{
    extern __shared__ float sm[];
    constexpr int AS = 128 * 36;
    constexpr int BS = B_KN ? (32 * 68) : (64 * 36);
    float* AsR = sm;
    float* AsI = sm + 2 * AS;
    float* BsR = sm + 4 * AS;
    float* BsI = sm + 4 * AS + 2 * BS;

    const int tid  = threadIdx.x;
    const int lane = tid & 31;
    const int warp = tid >> 5;
    const int wm   = warp & 3;
    const int wn   = warp >> 2;
    const int grp  = lane >> 2;
    const int quad = lane & 3;

    const int bz = blockIdx.z;
    const int zb = bz >> 3, zh = bz & 7;
    const int m0 = blockIdx.y << 7;
    const int n0 = blockIdx.x << 6;

    const float* ArB = Ar + (size_t)zb * sA1 + (size_t)zh * sA2;
    const float* AiB = Ai + (size_t)zb * sA1 + (size_t)zh * sA2;
    const float* BrB = Br + (size_t)zb * sB1 + (size_t)zh * sB2;
    const float* BiB = Bi + (size_t)zb * sB1 + (size_t)zh * sB2;

    const uint32_t sAsR = (uint32_t)__cvta_generic_to_shared(AsR);
    const uint32_t sAsI = (uint32_t)__cvta_generic_to_shared(AsI);
    const uint32_t sBsR = (uint32_t)__cvta_generic_to_shared(BsR);
    const uint32_t sBsI = (uint32_t)__cvta_generic_to_shared(BsI);

    float cr[2][4][4], ci[2][4][4];
#pragma unroll
    for (int mi = 0; mi < 2; mi++)
#pragma unroll
        for (int ni = 0; ni < 4; ni++)
#pragma unroll
            for (int r = 0; r < 4; r++) { cr[mi][ni][r] = 0.f; ci[mi][ni][r] = 0.f; }

    const int NC = K >> 5;

    auto load_chunk = [&](int c, int buf) {
        const int k0 = c << 5;
#pragma unroll
        for (int j = 0; j < 4; j++) {
            int idx = tid + j * 256;
            int row = idx >> 3;
            int c4  = (idx & 7) << 2;
            uint32_t so = (uint32_t)((buf * AS + row * 36 + c4) * 4);
            cp16(sAsR + so, ArB + (size_t)(m0 + row) * lda + k0 + c4);
            cp16(sAsI + so, AiB + (size_t)(m0 + row) * lda + k0 + c4);
        }
        if (B_KN) {
#pragma unroll
            for (int j = 0; j < 2; j++) {
                int idx = tid + j * 256;
                int row = idx >> 4;
                int c4  = (idx & 15) << 2;
                uint32_t so = (uint32_t)((buf * BS + row * 68 + c4) * 4);
                cp16(sBsR + so, BrB + (size_t)(k0 + row) * ldb + n0 + c4);
                cp16(sBsI + so, BiB + (size_t)(k0 + row) * ldb + n0 + c4);
            }
        } else {
#pragma unroll
            for (int j = 0; j < 2; j++) {
                int idx = tid + j * 256;
                int row = idx >> 3;
                int c4  = (idx & 7) << 2;
                uint32_t so = (uint32_t)((buf * BS + row * 36 + c4) * 4);
                cp16(sBsR + so, BrB + (size_t)(n0 + row) * ldb + k0 + c4);
                cp16(sBsI + so, BiB + (size_t)(n0 + row) * ldb + k0 + c4);
            }
        }
    };

    auto ldA = [&](const float* p) -> uint32_t {
        return CVT_A ? f2tf(*p) : __float_as_uint(*p);
    };
    auto ldB = [&](const float* p) -> uint32_t {
        return CVT_B ? f2tf(*p) : __float_as_uint(*p);
    };

    load_chunk(0, 0);
    asm volatile("cp.async.commit_group;");

    for (int c = 0; c < NC; c++) {
        if (c + 1 < NC) load_chunk(c + 1, (c + 1) & 1);
        asm volatile("cp.async.commit_group;");
        asm volatile("cp.async.wait_group 1;");
        __syncthreads();

        const float* aR = AsR + (c & 1) * AS;
        const float* aI = AsI + (c & 1) * AS;
        const float* bR = BsR + (c & 1) * BS;
        const float* bI = BsI + (c & 1) * BS;

#pragma unroll
        for (int ks = 0; ks < 4; ks++) {
            const int kk = ks * 8 + quad;
            uint32_t afr[2][4], afi[2][4];
#pragma unroll
            for (int mi = 0; mi < 2; mi++) {
                int r0 = wm * 32 + mi * 16 + grp;
                afr[mi][0] = ldA(&aR[r0 * 36 + kk]);
                afr[mi][1] = ldA(&aR[(r0 + 8) * 36 + kk]);
                afr[mi][2] = ldA(&aR[r0 * 36 + kk + 4]);
                afr[mi][3] = ldA(&aR[(r0 + 8) * 36 + kk + 4]);
                afi[mi][0] = ldA(&aI[r0 * 36 + kk]);
                afi[mi][1] = ldA(&aI[(r0 + 8) * 36 + kk]);
                afi[mi][2] = ldA(&aI[r0 * 36 + kk + 4]);
                afi[mi][3] = ldA(&aI[(r0 + 8) * 36 + kk + 4]);
            }
#pragma unroll
            for (int ni = 0; ni < 4; ni++) {
                int nn = wn * 32 + ni * 8 + grp;
                uint32_t bfr[2], bfi[2], bfx[2];
                if (B_KN) {
                    bfr[0] = ldB(&bR[kk * 68 + nn]);
                    bfr[1] = ldB(&bR[(kk + 4) * 68 + nn]);
                    bfi[0] = ldB(&bI[kk * 68 + nn]);
                    bfi[1] = ldB(&bI[(kk + 4) * 68 + nn]);
                } else {
                    bfr[0] = ldB(&bR[nn * 36 + kk]);
                    bfr[1] = ldB(&bR[nn * 36 + kk + 4]);
                    bfi[0] = ldB(&bI[nn * 36 + kk]);
                    bfi[1] = ldB(&bI[nn * 36 + kk + 4]);
                }
                bfx[0] = bfi[0] ^ 0x80000000u;
                bfx[1] = bfi[1] ^ 0x80000000u;
#pragma unroll
                for (int mi = 0; mi < 2; mi++) {
                    mma8(cr[mi][ni], afr[mi], bfr);
                    mma8(cr[mi][ni], afi[mi], CONJ ? bfi : bfx);
                    mma8(ci[mi][ni], afi[mi], bfr);
                    mma8(ci[mi][ni], afr[mi], CONJ ? bfx : bfi);
                }
            }
        }
        __syncthreads();
    }

    // Epilogue
    float* CrB = Cr + (size_t)zb * sC1 + (size_t)zh * sC2;
    float* CiB = Ci + (size_t)zb * sC1 + (size_t)zh * sC2;
#pragma unroll
    for (int mi = 0; mi < 2; mi++) {
#pragma unroll
        for (int ni = 0; ni < 4; ni++) {
            int m = m0 + wm * 32 + mi * 16 + grp;
            int n = n0 + wn * 32 + ni * 8 + quad * 2;
            float br0 = 0.f, br1 = 0.f, bi0 = 0.f, bi1 = 0.f;
            if (biasr) {
                br0 = biasr[n]; br1 = biasr[n + 1];
                bi0 = biasi[n]; bi1 = biasi[n + 1];
            }
            float vr0 = cr[mi][ni][0] * alpha + br0;
            float vr1 = cr[mi][ni][1] * alpha + br1;
            float vr2 = cr[mi][ni][2] * alpha + br0;
            float vr3 = cr[mi][ni][3] * alpha + br1;
            float vi0 = ci[mi][ni][0] * alpha + bi0;
            float vi1 = ci[mi][ni][1] * alpha + bi1;
            float vi2 = ci[mi][ni][2] * alpha + bi0;
            float vi3 = ci[mi][ni][3] * alpha + bi1;
            if (ROUND_C) {
                vr0 = tfround(vr0); vr1 = tfround(vr1);
                vr2 = tfround(vr2); vr3 = tfround(vr3);
                vi0 = tfround(vi0); vi1 = tfround(vi1);
                vi2 = tfround(vi2); vi3 = tfround(vi3);
            }
            float2 v;
            v.x = vr0; v.y = vr1;
            *(float2*)(CrB + (size_t)m * ldc + n) = v;
            v.x = vr2; v.y = vr3;
            *(float2*)(CrB + (size_t)(m + 8) * ldc + n) = v;
            v.x = vi0; v.y = vi1;
            *(float2*)(CiB + (size_t)m * ldc + n) = v;
            v.x = vi2; v.y = vi3;
            *(float2*)(CiB + (size_t)(m + 8) * ldc + n) = v;
        }
    }
}

// ---------------------------------------------------------------------------
// Fused softmax + head-average. One block per (t, b, comp).
// For each of the 8 heads: softmax the (bh, t) row of g_aw in place,
// accumulate the head average, write avg to d_out tail.
// ---------------------------------------------------------------------------
__global__ __launch_bounds__(256) void softmax_avg(float* __restrict__ out)
{
    const int t = blockIdx.x;
    const int b = blockIdx.y;
    const int comp = blockIdx.z;
    float* buf = comp ? g_aw_i : g_aw_r;

    const int tid = threadIdx.x;
    const int lane = tid & 31;
    const int wrp = tid >> 5;

    __shared__ float red[16];   // [0..7] max partials, [8..15] sum partials

    float4 acc = {0.f, 0.f, 0.f, 0.f};

#pragma unroll 1
    for (int h = 0; h < H_; h++) {
        float* p = buf + ((size_t)(b * H_ + h) * T_ + t) * T_;
        float4 v = *(const float4*)&p[tid << 2];

        float m = fmaxf(fmaxf(v.x, v.y), fmaxf(v.z, v.w));
#pragma unroll
        for (int o = 16; o > 0; o >>= 1)
            m = fmaxf(m, __shfl_xor_sync(0xffffffffu, m, o));
        if (lane == 0) red[wrp] = m;
        __syncthreads();
        float rm = fmaxf(fmaxf(fmaxf(red[0], red[1]), fmaxf(red[2], red[3])),
                         fmaxf(fmaxf(red[4], red[5]), fmaxf(red[6], red[7])));

        float4 e;
        e.x = __expf(v.x - rm);
        e.y = __expf(v.y - rm);
        e.z = __expf(v.z - rm);
        e.w = __expf(v.w - rm);
        float s = e.x + e.y + e.z + e.w;
#pragma unroll
        for (int o = 16; o > 0; o >>= 1)
            s += __shfl_xor_sync(0xffffffffu, s, o);
        if (lane == 0) red[8 + wrp] = s;
        __syncthreads();
        float inv = 1.0f / (red[8] + red[9] + red[10] + red[11] +
                            red[12] + red[13] + red[14] + red[15]);

        e.x *= inv; e.y *= inv; e.z *= inv; e.w *= inv;
        *(float4*)&p[tid << 2] = e;
        acc.x += e.x; acc.y += e.y; acc.z += e.z; acc.w += e.w;
        __syncthreads();
    }

    const float inv8 = 1.0f / (float)H_;
    acc.x *= inv8; acc.y *= inv8; acc.z *= inv8; acc.w *= inv8;
    size_t o = OUT_OFF2 + (size_t)comp * BTT_ + ((size_t)b * T_ + t) * T_ + (tid << 2);
    *(float4*)&out[o] = acc;
}

// ---------------------------------------------------------------------------
extern "C" void kernel_launch(void* const* d_in, const int* in_sizes, int n_in,
                              void* d_out, int out_size)
{
    const float* query_r = (const float*)d_in[0];
    const float* query_i = (const float*)d_in[1];
    const float* W_qkv_r = (const float*)d_in[2];
    const float* W_qkv_i = (const float*)d_in[3];
    const float* b_qkv_r = (const float*)d_in[4];
    const float* b_qkv_i = (const float*)d_in[5];
    const float* W_out_r = (const float*)d_in[6];
    const float* W_out_i = (const float*)d_in[7];
    const float* b_out_r = (const float*)d_in[8];
    const float* b_out_i = (const float*)d_in[9];
    float* out = (float*)d_out;

    float *gqkvr, *gqkvi, *gawr, *gawi, *gatr, *gati;
    float *gqtr, *gqti, *gwqr, *gwqi, *gwor, *gwoi;
    cudaGetSymbolAddress((void**)&gqkvr, g_qkv_r);
    cudaGetSymbolAddress((void**)&gqkvi, g_qkv_i);
    cudaGetSymbolAddress((void**)&gawr, g_aw_r);
    cudaGetSymbolAddress((void**)&gawi, g_aw_i);
    cudaGetSymbolAddress((void**)&gatr, g_attn_r);
    cudaGetSymbolAddress((void**)&gati, g_attn_i);
    cudaGetSymbolAddress((void**)&gqtr, g_qt_r);
    cudaGetSymbolAddress((void**)&gqti, g_qt_i);
    cudaGetSymbolAddress((void**)&gwqr, g_wqkv_r);
    cudaGetSymbolAddress((void**)&gwqi, g_wqkv_i);
    cudaGetSymbolAddress((void**)&gwor, g_wout_r);
    cudaGetSymbolAddress((void**)&gwoi, g_wout_i);

    const int SMEM_NK = (4 * 128 * 36 + 4 * 64 * 36) * 4;   // 110592 B
    const int SMEM_KN = (4 * 128 * 36 + 4 * 32 * 68) * 4;   // 108544 B

    cudaFuncSetAttribute((const void*)cmma_kernel<false, false, false, false, true>,
                         cudaFuncAttributeMaxDynamicSharedMemorySize, SMEM_NK);
    cudaFuncSetAttribute((const void*)cmma_kernel<false, false, false, false, false>,
                         cudaFuncAttributeMaxDynamicSharedMemorySize, SMEM_NK);
    cudaFuncSetAttribute((const void*)cmma_kernel<true, false, false, false, false>,
                         cudaFuncAttributeMaxDynamicSharedMemorySize, SMEM_NK);
    cudaFuncSetAttribute((const void*)cmma_kernel<true, true, true, false, true>,
                         cudaFuncAttributeMaxDynamicSharedMemorySize, SMEM_KN);

    dim3 blk(256);

    // 0) Pre-round GEMM inputs to tf32 values
    round_kernel<<<(M_ * E_ / 4 + 255) / 256, blk>>>(query_r, gqtr, M_ * E_ / 4);
    round_kernel<<<(M_ * E_ / 4 + 255) / 256, blk>>>(query_i, gqti, M_ * E_ / 4);
    round_kernel<<<(K3E * E_ / 4 + 255) / 256, blk>>>(W_qkv_r, gwqr, K3E * E_ / 4);
    round_kernel<<<(K3E * E_ / 4 + 255) / 256, blk>>>(W_qkv_i, gwqi, K3E * E_ / 4);
    round_kernel<<<(E_ * E_ / 4 + 255) / 256, blk>>>(W_out_r, gwor, E_ * E_ / 4);
    round_kernel<<<(E_ * E_ / 4 + 255) / 256, blk>>>(W_out_i, gwoi, E_ * E_ / 4);

    // 1) QKV complex linear (pre-rounded operands; rounded outputs)
    cmma_kernel<false, false, false, false, true>
        <<<dim3(K3E / 64, M_ / 128, 1), blk, SMEM_NK>>>(
        gqtr, gqti, E_, 0, 0,
        gwqr, gwqi, E_, 0, 0,
        gqkvr, gqkvi, K3E, 0, 0,
        b_qkv_r, b_qkv_i, 1.0f, E_);

    // 2) Scores (operands pre-rounded; logits fp32)
    cmma_kernel<true, false, false, false, false>
        <<<dim3(T_ / 64, T_ / 128, BH_), blk, SMEM_NK>>>(
        gqkvr, gqkvi, (long)B_ * K3E, K3E, D_,
        gqkvr + E_, gqkvi + E_, (long)B_ * K3E, K3E, D_,
        gawr, gawi, T_, (long)8 * TT_, (long)TT_,
        nullptr, nullptr, SCALE_, D_);

    // 3) Fused softmax + head-average (p in place; avg -> d_out tail)
    softmax_avg<<<dim3(T_, B_, 2), blk>>>(out);

    // 4) PV (A=p needs cvt; V pre-rounded; attn stored rounded, [T,B,E])
    cmma_kernel<true, true, true, false, true>
        <<<dim3(1, T_ / 128, BH_), blk, SMEM_KN>>>(
        gawr, gawi, T_, (long)8 * TT_, (long)TT_,
        gqkvr + 2 * E_, gqkvi + 2 * E_, (long)B_ * K3E, K3E, D_,
        gatr, gati, (long)B_ * E_, E_, D_,
        nullptr, nullptr, 1.0f, T_);

    // 5) Output complex linear -> d_out head
    cmma_kernel<false, false, false, false, false>
        <<<dim3(E_ / 64, M_ / 128, 1), blk, SMEM_NK>>>(
        gatr, gati, E_, 0, 0,
        gwor, gwoi, E_, 0, 0,
        out, out + (size_t)M_ * E_, E_, 0, 0,
        b_out_r, b_out_i, 1.0f, E_);
}